// round 6
// baseline (speedup 1.0000x reference)
#include <cuda_runtime.h>
#include <cstdint>

#define N_NODES 100000
#define IN_CH   512
#define HID     16
#define OUT_CH  64
#define MAX_E   3200000
#define NBLK    ((N_NODES + 255) / 256)   // 391 row-tiles / scan blocks
#define GEMM_A  235                       // tiles in CK1 (with hist)
#define GEMM_B  (NBLK - GEMM_A)           // tiles in CK2 (with scatter)

typedef unsigned long long u64;

// ---------------- device scratch (static, no allocation) ----------------
__device__ float g_dinv[N_NODES];
__device__ int   g_cnt[N_NODES];
__device__ int   g_pre[N_NODES];
__device__ int   g_bsum[NBLK];
__device__ int   g_boff[NBLK];
__device__ int   g_rowptr[N_NODES + 1];
__device__ int   g_cur[N_NODES];
__device__ int2  g_csr[MAX_E];            // (src, w-bits) per edge, bucketed by dst
__device__ float g_h1[N_NODES * HID];     // layer1 linear out
__device__ float g_hr[N_NODES * HID];     // relu'd hidden after layer1 conv

// ---------------- f32x2 helpers ----------------
__device__ __forceinline__ u64 pack2(float lo, float hi) {
    u64 r; asm("mov.b64 %0, {%1, %2};" : "=l"(r) : "f"(lo), "f"(hi)); return r;
}
__device__ __forceinline__ u64 fma2(u64 a, u64 b, u64 c) {
    u64 d; asm("fma.rn.f32x2 %0, %1, %2, %3;" : "=l"(d) : "l"(a), "l"(b), "l"(c)); return d;
}
__device__ __forceinline__ float2 unpack2(u64 v) {
    float2 f; asm("mov.b64 {%0, %1}, %2;" : "=f"(f.x), "=f"(f.y) : "l"(v)); return f;
}

// ---------------- GEMM1 tile (f32x2): 256 rows x 16 out, K=512 ----------------
#define XT_STRIDE 260   // 1040B row pitch, 16B aligned
__device__ __forceinline__ void gemm1_tile(const float* __restrict__ x,
                                           const float* __restrict__ W,
                                           int n, int tile) {
    __shared__ __align__(16) float xT[16 * XT_STRIDE];  // [k][row]
    __shared__ __align__(16) u64   Wc2[16 * HID];       // [k][j] broadcast pairs (w,w)

    const int t = threadIdx.x;
    const int rowBase = tile * 256;
    const int jg = t & 3;   // col group (4 cols)
    const int rg = t >> 2;  // row group (4 rows)

    u64 accp[2][4];  // [row-pair][col], rows (rg*4+0,rg*4+1) and (rg*4+2,rg*4+3)
#pragma unroll
    for (int p = 0; p < 2; p++)
#pragma unroll
        for (int j = 0; j < 4; j++) accp[p][j] = 0ull;

    for (int kk = 0; kk < IN_CH; kk += 16) {
        {   // stage W broadcast pairs: Wc2[k][j] = (w,w)
            float w = W[(kk + (t >> 4)) * HID + (t & 15)];
            Wc2[t] = pack2(w, w);
        }
#pragma unroll
        for (int p = 0; p < 4; p++) {
            int rlocal = (t >> 2) + p * 64;
            int k4 = (t & 3) * 4;
            int grow = rowBase + rlocal;
            float4 v = make_float4(0.f, 0.f, 0.f, 0.f);
            if (grow < n)
                v = *reinterpret_cast<const float4*>(&x[(size_t)grow * IN_CH + kk + k4]);
            xT[(k4 + 0) * XT_STRIDE + rlocal] = v.x;
            xT[(k4 + 1) * XT_STRIDE + rlocal] = v.y;
            xT[(k4 + 2) * XT_STRIDE + rlocal] = v.z;
            xT[(k4 + 3) * XT_STRIDE + rlocal] = v.w;
        }
        __syncthreads();
#pragma unroll
        for (int k = 0; k < 16; k++) {
            // x row pairs come packed straight from shared (rows contiguous)
            ulonglong2 xp = *reinterpret_cast<const ulonglong2*>(&xT[k * XT_STRIDE + rg * 4]);
            ulonglong2 wa = *reinterpret_cast<const ulonglong2*>(&Wc2[k * HID + jg * 4]);
            ulonglong2 wb = *reinterpret_cast<const ulonglong2*>(&Wc2[k * HID + jg * 4 + 2]);
            accp[0][0] = fma2(xp.x, wa.x, accp[0][0]);
            accp[0][1] = fma2(xp.x, wa.y, accp[0][1]);
            accp[0][2] = fma2(xp.x, wb.x, accp[0][2]);
            accp[0][3] = fma2(xp.x, wb.y, accp[0][3]);
            accp[1][0] = fma2(xp.y, wa.x, accp[1][0]);
            accp[1][1] = fma2(xp.y, wa.y, accp[1][1]);
            accp[1][2] = fma2(xp.y, wb.x, accp[1][2]);
            accp[1][3] = fma2(xp.y, wb.y, accp[1][3]);
        }
        __syncthreads();
    }
    // unpack and store: accp[p][j] = (row rg*4+2p, row rg*4+2p+1) col jg*4+j
#pragma unroll
    for (int p = 0; p < 2; p++) {
        float2 c0 = unpack2(accp[p][0]);
        float2 c1 = unpack2(accp[p][1]);
        float2 c2 = unpack2(accp[p][2]);
        float2 c3 = unpack2(accp[p][3]);
        int r0 = rowBase + rg * 4 + 2 * p;
        if (r0 < n)
            reinterpret_cast<float4*>(&g_h1[(size_t)r0 * HID])[jg] =
                make_float4(c0.x, c1.x, c2.x, c3.x);
        if (r0 + 1 < n)
            reinterpret_cast<float4*>(&g_h1[(size_t)(r0 + 1) * HID])[jg] =
                make_float4(c0.y, c1.y, c2.y, c3.y);
    }
}

// ---------------- combined kernels: gemm tiles first, then build work ----------------
__global__ void __launch_bounds__(256) k_ck1(const float* __restrict__ x,
                                             const float* __restrict__ W,
                                             const int* __restrict__ dst,
                                             int n, int e, int gemmBlocks) {
    if ((int)blockIdx.x < gemmBlocks) {
        gemm1_tile(x, W, n, blockIdx.x);
    } else {
        int i = ((int)blockIdx.x - gemmBlocks) * 256 + threadIdx.x;
        if (i < e) atomicAdd(&g_cnt[dst[i]], 1);
    }
}

__global__ void __launch_bounds__(256) k_ck2(const float* __restrict__ x,
                                             const float* __restrict__ W,
                                             const int* __restrict__ src,
                                             const int* __restrict__ dst,
                                             int n, int e, int gemmBlocks, int tileBase) {
    if ((int)blockIdx.x < gemmBlocks) {
        gemm1_tile(x, W, n, tileBase + blockIdx.x);
    } else {
        int i = ((int)blockIdx.x - gemmBlocks) * 256 + threadIdx.x;
        if (i < e) {
            int s = src[i];
            int d = dst[i];
            float w = g_dinv[s] * g_dinv[d];
            int pos = atomicAdd(&g_cur[d], 1);
            g_csr[pos] = make_int2(s, __float_as_int(w));
        }
    }
}

// ---------------- CSR build scaffolding ----------------
__global__ void k_zero_cnt(int n) {
    int i = blockIdx.x * blockDim.x + threadIdx.x;
    if (i < n) g_cnt[i] = 0;
}

__global__ void __launch_bounds__(256) k_scanA(int n) {
    __shared__ int s[256];
    int t = threadIdx.x;
    int i = blockIdx.x * 256 + t;
    int v = (i < n) ? g_cnt[i] : 0;
    s[t] = v;
    __syncthreads();
#pragma unroll
    for (int off = 1; off < 256; off <<= 1) {
        int add = (t >= off) ? s[t - off] : 0;
        __syncthreads();
        s[t] += add;
        __syncthreads();
    }
    if (i < n) g_pre[i] = s[t] - v;               // exclusive
    if (t == 255) g_bsum[blockIdx.x] = s[255];
}

__global__ void __launch_bounds__(512) k_scanB(int nb) {
    __shared__ int s[512];
    int t = threadIdx.x;
    int v = (t < nb) ? g_bsum[t] : 0;
    s[t] = v;
    __syncthreads();
#pragma unroll
    for (int off = 1; off < 512; off <<= 1) {
        int add = (t >= off) ? s[t - off] : 0;
        __syncthreads();
        s[t] += add;
        __syncthreads();
    }
    if (t < nb) g_boff[t] = s[t] - v;             // exclusive
}

__global__ void k_scanC(int n) {
    int i = blockIdx.x * blockDim.x + threadIdx.x;
    if (i >= n) return;
    int rp = g_pre[i] + g_boff[i >> 8];
    g_rowptr[i] = rp;
    g_cur[i] = rp;
    g_dinv[i] = rsqrtf((float)g_cnt[i] + 1.0f);   // +1 self loop
    if (i == n - 1) g_rowptr[n] = rp + g_cnt[i];
}

// ---------------- gather layer 1 (fused self-loop + bias + relu) ----------------
__global__ void __launch_bounds__(256) k_gather1(const float* __restrict__ b1, int n) {
    int wid = (blockIdx.x * 256 + threadIdx.x) >> 5;
    if (wid >= n) return;
    int lane = threadIdx.x & 31;
    int ql = lane & 7, qh = lane >> 3;
    int row = g_rowptr[wid], end = g_rowptr[wid + 1];

    float2 acc = make_float2(0.f, 0.f);
    for (int i = row + qh; i < end; i += 4) {
        int2 ec = g_csr[i];
        float w = __int_as_float(ec.y);
        float2 hv = *reinterpret_cast<const float2*>(&g_h1[(size_t)ec.x * HID + ql * 2]);
        acc.x += w * hv.x;
        acc.y += w * hv.y;
    }
    acc.x += __shfl_xor_sync(0xffffffffu, acc.x, 8);
    acc.y += __shfl_xor_sync(0xffffffffu, acc.y, 8);
    acc.x += __shfl_xor_sync(0xffffffffu, acc.x, 16);
    acc.y += __shfl_xor_sync(0xffffffffu, acc.y, 16);

    float di = g_dinv[wid];
    float sl = di * di;
    float2 hv = *reinterpret_cast<const float2*>(&g_h1[(size_t)wid * HID + ql * 2]);
    float2 bb = *reinterpret_cast<const float2*>(&b1[ql * 2]);
    float2 r;
    r.x = fmaxf(acc.x + hv.x * sl + bb.x, 0.f);
    r.y = fmaxf(acc.y + hv.y * sl + bb.y, 0.f);
    if (qh == 0)
        *reinterpret_cast<float2*>(&g_hr[(size_t)wid * HID + ql * 2]) = r;
}

// ---------------- gather layer 2 (fused W2 GEMM + log-softmax) ----------------
__global__ void __launch_bounds__(256) k_gather2(const float* __restrict__ W2,
                                                 const float* __restrict__ b2,
                                                 float* __restrict__ out, int n) {
    __shared__ float W2s[HID * OUT_CH];  // 4 KB
    for (int i = threadIdx.x; i < HID * OUT_CH; i += 256) W2s[i] = W2[i];
    __syncthreads();

    int wid = (blockIdx.x * 256 + threadIdx.x) >> 5;
    if (wid >= n) return;
    int lane = threadIdx.x & 31;
    int ql = lane & 7, qh = lane >> 3;
    int row = g_rowptr[wid], end = g_rowptr[wid + 1];

    float2 acc = make_float2(0.f, 0.f);
    for (int i = row + qh; i < end; i += 4) {
        int2 ec = g_csr[i];
        float w = __int_as_float(ec.y);
        float2 hv = *reinterpret_cast<const float2*>(&g_hr[(size_t)ec.x * HID + ql * 2]);
        acc.x += w * hv.x;
        acc.y += w * hv.y;
    }
    acc.x += __shfl_xor_sync(0xffffffffu, acc.x, 8);
    acc.y += __shfl_xor_sync(0xffffffffu, acc.y, 8);
    acc.x += __shfl_xor_sync(0xffffffffu, acc.x, 16);
    acc.y += __shfl_xor_sync(0xffffffffu, acc.y, 16);

    float di = g_dinv[wid];
    float sl = di * di;
    float2 hv = *reinterpret_cast<const float2*>(&g_hr[(size_t)wid * HID + ql * 2]);
    float tx = acc.x + hv.x * sl;   // t[2*ql] (lanes 0..7 hold the 16-dim vector)
    float ty = acc.y + hv.y * sl;   // t[2*ql+1]

    float y0 = b2[lane];
    float y1 = b2[lane + 32];
#pragma unroll
    for (int k = 0; k < 8; k++) {
        float a = __shfl_sync(0xffffffffu, tx, k);
        float b = __shfl_sync(0xffffffffu, ty, k);
        y0 += a * W2s[(2 * k) * OUT_CH + lane]      + b * W2s[(2 * k + 1) * OUT_CH + lane];
        y1 += a * W2s[(2 * k) * OUT_CH + lane + 32] + b * W2s[(2 * k + 1) * OUT_CH + lane + 32];
    }
    float m = fmaxf(y0, y1);
#pragma unroll
    for (int o = 16; o; o >>= 1) m = fmaxf(m, __shfl_xor_sync(0xffffffffu, m, o));
    float se = expf(y0 - m) + expf(y1 - m);
#pragma unroll
    for (int o = 16; o; o >>= 1) se += __shfl_xor_sync(0xffffffffu, se, o);
    float lg = m + logf(se);
    out[(size_t)wid * OUT_CH + lane]      = y0 - lg;
    out[(size_t)wid * OUT_CH + lane + 32] = y1 - lg;
}

// ---------------- launch ----------------
extern "C" void kernel_launch(void* const* d_in, const int* in_sizes, int n_in,
                              void* d_out, int out_size) {
    const float* x    = (const float*)d_in[0];
    const int*   ei   = (const int*)d_in[1];     // int32 (JAX x64 disabled)
    const float* W1   = (const float*)d_in[2];
    const float* b1   = (const float*)d_in[3];
    const float* W2   = (const float*)d_in[4];
    const float* b2   = (const float*)d_in[5];
    float* out        = (float*)d_out;

    const int n = in_sizes[0] / IN_CH;       // 100000
    const int e = in_sizes[1] / 2;           // 3200000
    const int* src = ei;
    const int* dst = ei + e;

    const int TB = 256;
    int gb_n = (n + TB - 1) / TB;            // == NBLK
    int gb_e = (e + TB - 1) / TB;            // 12500
    int gb_w = (n * 32 + TB - 1) / TB;       // warp-per-node kernels

    k_zero_cnt<<<gb_n, TB>>>(n);
    // CK1: gemm tiles [0, GEMM_A) co-scheduled with the dst histogram
    k_ck1<<<GEMM_A + gb_e, TB>>>(x, W1, dst, n, e, GEMM_A);
    k_scanA<<<gb_n, TB>>>(n);
    k_scanB<<<1, 512>>>(gb_n);
    k_scanC<<<gb_n, TB>>>(n);
    // CK2: gemm tiles [GEMM_A, NBLK) co-scheduled with the CSR scatter
    k_ck2<<<GEMM_B + gb_e, TB>>>(x, W1, src, dst, n, e, GEMM_B, GEMM_A);
    k_gather1<<<gb_w, TB>>>(b1, n);
    k_gather2<<<gb_w, TB>>>(W2, b2, out, n);
}

// round 7
// speedup vs baseline: 1.0128x; 1.0128x over previous
#include <cuda_runtime.h>
#include <cstdint>

#define N_NODES 100000
#define IN_CH   512
#define HID     16
#define OUT_CH  64
#define MAX_E   3200000
#define NBLK    ((N_NODES + 255) / 256)   // 391 row-tiles / scan blocks

typedef unsigned long long u64;

// ---------------- device scratch (static, no allocation) ----------------
__device__ float g_dinv[N_NODES];
__device__ int   g_cnt[N_NODES];
__device__ int   g_pre[N_NODES];
__device__ int   g_bsum[NBLK];
__device__ int   g_boff[NBLK];
__device__ int   g_rowptr[N_NODES + 1];
__device__ int   g_cur[N_NODES];
__device__ int2  g_csr[MAX_E];            // (src, w-bits) per edge, bucketed by dst
__device__ float g_h1[N_NODES * HID];     // layer1 linear out
__device__ float g_hr[N_NODES * HID];     // relu'd hidden after layer1 conv

// ---------------- f32x2 helpers ----------------
__device__ __forceinline__ u64 pack2(float lo, float hi) {
    u64 r; asm("mov.b64 %0, {%1, %2};" : "=l"(r) : "f"(lo), "f"(hi)); return r;
}
__device__ __forceinline__ u64 fma2(u64 a, u64 b, u64 c) {
    u64 d; asm("fma.rn.f32x2 %0, %1, %2, %3;" : "=l"(d) : "l"(a), "l"(b), "l"(c)); return d;
}
__device__ __forceinline__ float2 unpack2(u64 v) {
    float2 f; asm("mov.b64 {%0, %1}, %2;" : "=f"(f.x), "=f"(f.y) : "l"(v)); return f;
}

// ---------------- GEMM1 (f32x2): h1 = x @ W1, 256 rows x 16 out per block ----------------
#define XT_STRIDE 260   // 1040B row pitch, 16B aligned
__global__ void __launch_bounds__(256) k_gemm1(const float* __restrict__ x,
                                               const float* __restrict__ W, int n) {
    __shared__ __align__(16) float xT[16 * XT_STRIDE];  // [k][row]
    __shared__ __align__(16) u64   Wc2[16 * HID];       // [k][j] broadcast pairs (w,w)

    const int t = threadIdx.x;
    const int rowBase = blockIdx.x * 256;
    const int jg = t & 3;   // col group (4 cols)
    const int rg = t >> 2;  // row group (4 rows)

    u64 accp[2][4];  // [row-pair][col]
#pragma unroll
    for (int p = 0; p < 2; p++)
#pragma unroll
        for (int j = 0; j < 4; j++) accp[p][j] = 0ull;

    for (int kk = 0; kk < IN_CH; kk += 16) {
        {   // stage W broadcast pairs: Wc2[k][j] = (w,w)
            float w = W[(kk + (t >> 4)) * HID + (t & 15)];
            Wc2[t] = pack2(w, w);
        }
#pragma unroll
        for (int p = 0; p < 4; p++) {
            int rlocal = (t >> 2) + p * 64;
            int k4 = (t & 3) * 4;
            int grow = rowBase + rlocal;
            float4 v = make_float4(0.f, 0.f, 0.f, 0.f);
            if (grow < n)
                v = *reinterpret_cast<const float4*>(&x[(size_t)grow * IN_CH + kk + k4]);
            xT[(k4 + 0) * XT_STRIDE + rlocal] = v.x;
            xT[(k4 + 1) * XT_STRIDE + rlocal] = v.y;
            xT[(k4 + 2) * XT_STRIDE + rlocal] = v.z;
            xT[(k4 + 3) * XT_STRIDE + rlocal] = v.w;
        }
        __syncthreads();
#pragma unroll
        for (int k = 0; k < 16; k++) {
            // x row pairs come packed straight from shared (rows contiguous)
            ulonglong2 xp = *reinterpret_cast<const ulonglong2*>(&xT[k * XT_STRIDE + rg * 4]);
            ulonglong2 wa = *reinterpret_cast<const ulonglong2*>(&Wc2[k * HID + jg * 4]);
            ulonglong2 wb = *reinterpret_cast<const ulonglong2*>(&Wc2[k * HID + jg * 4 + 2]);
            accp[0][0] = fma2(xp.x, wa.x, accp[0][0]);
            accp[0][1] = fma2(xp.x, wa.y, accp[0][1]);
            accp[0][2] = fma2(xp.x, wb.x, accp[0][2]);
            accp[0][3] = fma2(xp.x, wb.y, accp[0][3]);
            accp[1][0] = fma2(xp.y, wa.x, accp[1][0]);
            accp[1][1] = fma2(xp.y, wa.y, accp[1][1]);
            accp[1][2] = fma2(xp.y, wb.x, accp[1][2]);
            accp[1][3] = fma2(xp.y, wb.y, accp[1][3]);
        }
        __syncthreads();
    }
#pragma unroll
    for (int p = 0; p < 2; p++) {
        float2 c0 = unpack2(accp[p][0]);
        float2 c1 = unpack2(accp[p][1]);
        float2 c2 = unpack2(accp[p][2]);
        float2 c3 = unpack2(accp[p][3]);
        int r0 = rowBase + rg * 4 + 2 * p;
        if (r0 < n)
            reinterpret_cast<float4*>(&g_h1[(size_t)r0 * HID])[jg] =
                make_float4(c0.x, c1.x, c2.x, c3.x);
        if (r0 + 1 < n)
            reinterpret_cast<float4*>(&g_h1[(size_t)(r0 + 1) * HID])[jg] =
                make_float4(c0.y, c1.y, c2.y, c3.y);
    }
}

// ---------------- CSR build ----------------
__global__ void k_zero_cnt(int n) {
    int i = blockIdx.x * blockDim.x + threadIdx.x;
    if (i < n) g_cnt[i] = 0;
}

__global__ void k_hist(const int* __restrict__ dst, int e) {
    int i = blockIdx.x * blockDim.x + threadIdx.x;
    if (i < e) atomicAdd(&g_cnt[dst[i]], 1);
}

__global__ void __launch_bounds__(256) k_scanA(int n) {
    __shared__ int s[256];
    int t = threadIdx.x;
    int i = blockIdx.x * 256 + t;
    int v = (i < n) ? g_cnt[i] : 0;
    s[t] = v;
    __syncthreads();
#pragma unroll
    for (int off = 1; off < 256; off <<= 1) {
        int add = (t >= off) ? s[t - off] : 0;
        __syncthreads();
        s[t] += add;
        __syncthreads();
    }
    if (i < n) g_pre[i] = s[t] - v;               // exclusive
    if (t == 255) g_bsum[blockIdx.x] = s[255];
}

__global__ void __launch_bounds__(512) k_scanB(int nb) {
    __shared__ int s[512];
    int t = threadIdx.x;
    int v = (t < nb) ? g_bsum[t] : 0;
    s[t] = v;
    __syncthreads();
#pragma unroll
    for (int off = 1; off < 512; off <<= 1) {
        int add = (t >= off) ? s[t - off] : 0;
        __syncthreads();
        s[t] += add;
        __syncthreads();
    }
    if (t < nb) g_boff[t] = s[t] - v;             // exclusive
}

__global__ void k_scanC(int n) {
    int i = blockIdx.x * blockDim.x + threadIdx.x;
    if (i >= n) return;
    int rp = g_pre[i] + g_boff[i >> 8];
    g_rowptr[i] = rp;
    g_cur[i] = rp;
    g_dinv[i] = rsqrtf((float)g_cnt[i] + 1.0f);   // +1 self loop
    if (i == n - 1) g_rowptr[n] = rp + g_cnt[i];
}

__global__ void k_scatter(const int* __restrict__ src,
                          const int* __restrict__ dst, int e) {
    int i = blockIdx.x * blockDim.x + threadIdx.x;
    if (i >= e) return;
    int s = src[i];
    int d = dst[i];
    float w = g_dinv[s] * g_dinv[d];
    int pos = atomicAdd(&g_cur[d], 1);
    g_csr[pos] = make_int2(s, __float_as_int(w));
}

// ---------------- gather layer 1 (fused self-loop + bias + relu) ----------------
__global__ void __launch_bounds__(256) k_gather1(const float* __restrict__ b1, int n) {
    int wid = (blockIdx.x * 256 + threadIdx.x) >> 5;
    if (wid >= n) return;
    int lane = threadIdx.x & 31;
    int ql = lane & 7, qh = lane >> 3;
    int row = g_rowptr[wid], end = g_rowptr[wid + 1];

    float2 acc = make_float2(0.f, 0.f);
    for (int i = row + qh; i < end; i += 4) {
        int2 ec = g_csr[i];
        float w = __int_as_float(ec.y);
        float2 hv = *reinterpret_cast<const float2*>(&g_h1[(size_t)ec.x * HID + ql * 2]);
        acc.x += w * hv.x;
        acc.y += w * hv.y;
    }
    acc.x += __shfl_xor_sync(0xffffffffu, acc.x, 8);
    acc.y += __shfl_xor_sync(0xffffffffu, acc.y, 8);
    acc.x += __shfl_xor_sync(0xffffffffu, acc.x, 16);
    acc.y += __shfl_xor_sync(0xffffffffu, acc.y, 16);

    float di = g_dinv[wid];
    float sl = di * di;
    float2 hv = *reinterpret_cast<const float2*>(&g_h1[(size_t)wid * HID + ql * 2]);
    float2 bb = *reinterpret_cast<const float2*>(&b1[ql * 2]);
    float2 r;
    r.x = fmaxf(acc.x + hv.x * sl + bb.x, 0.f);
    r.y = fmaxf(acc.y + hv.y * sl + bb.y, 0.f);
    if (qh == 0)
        *reinterpret_cast<float2*>(&g_hr[(size_t)wid * HID + ql * 2]) = r;
}

// ---------------- gather layer 2 (fused W2 GEMM + log-softmax) ----------------
__global__ void __launch_bounds__(256) k_gather2(const float* __restrict__ W2,
                                                 const float* __restrict__ b2,
                                                 float* __restrict__ out, int n) {
    __shared__ float W2s[HID * OUT_CH];  // 4 KB
    for (int i = threadIdx.x; i < HID * OUT_CH; i += 256) W2s[i] = W2[i];
    __syncthreads();

    int wid = (blockIdx.x * 256 + threadIdx.x) >> 5;
    if (wid >= n) return;
    int lane = threadIdx.x & 31;
    int ql = lane & 7, qh = lane >> 3;
    int row = g_rowptr[wid], end = g_rowptr[wid + 1];

    float2 acc = make_float2(0.f, 0.f);
    for (int i = row + qh; i < end; i += 4) {
        int2 ec = g_csr[i];
        float w = __int_as_float(ec.y);
        float2 hv = *reinterpret_cast<const float2*>(&g_hr[(size_t)ec.x * HID + ql * 2]);
        acc.x += w * hv.x;
        acc.y += w * hv.y;
    }
    acc.x += __shfl_xor_sync(0xffffffffu, acc.x, 8);
    acc.y += __shfl_xor_sync(0xffffffffu, acc.y, 8);
    acc.x += __shfl_xor_sync(0xffffffffu, acc.x, 16);
    acc.y += __shfl_xor_sync(0xffffffffu, acc.y, 16);

    float di = g_dinv[wid];
    float sl = di * di;
    float2 hv = *reinterpret_cast<const float2*>(&g_hr[(size_t)wid * HID + ql * 2]);
    float tx = acc.x + hv.x * sl;   // t[2*ql] (lanes 0..7 hold the 16-dim vector)
    float ty = acc.y + hv.y * sl;   // t[2*ql+1]

    float y0 = b2[lane];
    float y1 = b2[lane + 32];
#pragma unroll
    for (int k = 0; k < 8; k++) {
        float a = __shfl_sync(0xffffffffu, tx, k);
        float b = __shfl_sync(0xffffffffu, ty, k);
        y0 += a * W2s[(2 * k) * OUT_CH + lane]      + b * W2s[(2 * k + 1) * OUT_CH + lane];
        y1 += a * W2s[(2 * k) * OUT_CH + lane + 32] + b * W2s[(2 * k + 1) * OUT_CH + lane + 32];
    }
    float m = fmaxf(y0, y1);
#pragma unroll
    for (int o = 16; o; o >>= 1) m = fmaxf(m, __shfl_xor_sync(0xffffffffu, m, o));
    float se = expf(y0 - m) + expf(y1 - m);
#pragma unroll
    for (int o = 16; o; o >>= 1) se += __shfl_xor_sync(0xffffffffu, se, o);
    float lg = m + logf(se);
    out[(size_t)wid * OUT_CH + lane]      = y0 - lg;
    out[(size_t)wid * OUT_CH + lane + 32] = y1 - lg;
}

// ---------------- launch ----------------
extern "C" void kernel_launch(void* const* d_in, const int* in_sizes, int n_in,
                              void* d_out, int out_size) {
    const float* x    = (const float*)d_in[0];
    const int*   ei   = (const int*)d_in[1];     // int32 (JAX x64 disabled)
    const float* W1   = (const float*)d_in[2];
    const float* b1   = (const float*)d_in[3];
    const float* W2   = (const float*)d_in[4];
    const float* b2   = (const float*)d_in[5];
    float* out        = (float*)d_out;

    const int n = in_sizes[0] / IN_CH;       // 100000
    const int e = in_sizes[1] / 2;           // 3200000
    const int* src = ei;
    const int* dst = ei + e;

    const int TB = 256;
    int gb_n = (n + TB - 1) / TB;            // == NBLK
    int gb_e = (e + TB - 1) / TB;
    int gb_w = (n * 32 + TB - 1) / TB;       // warp-per-node kernels

    // gemm1 is independent of the CSR chain — placed 4th so ncu (which keeps
    // capturing launch #4) profiles the heavy kernel this round.
    k_zero_cnt<<<gb_n, TB>>>(n);             // 1
    k_hist<<<gb_e, TB>>>(dst, e);            // 2
    k_scanA<<<gb_n, TB>>>(n);                // 3
    k_gemm1<<<(n + 255) / 256, 256>>>(x, W1, n);  // 4  <-- profiled
    k_scanB<<<1, 512>>>(gb_n);               // 5
    k_scanC<<<gb_n, TB>>>(n);                // 6
    k_scatter<<<gb_e, TB>>>(src, dst, e);    // 7
    k_gather1<<<gb_w, TB>>>(b1, n);          // 8
    k_gather2<<<gb_w, TB>>>(W2, b2, out, n); // 9
}